// round 2
// baseline (speedup 1.0000x reference)
#include <cuda_runtime.h>
#include <math.h>

#define BB 8
#define SS 2048
#define DDIM 256
#define HH 4
#define DH 64
#define NROWS (BB*SS)   // 16384

// ---------------- scratch (static device allocations; no cudaMalloc) -------
__device__ float g_qkv[(size_t)NROWS*768];      // [B*S, 768] interleaved (h,d,3)
__device__ float g_q  [(size_t)NROWS*DDIM];     // [B,H,S,Dh]
__device__ float g_k  [(size_t)NROWS*DDIM];     // [B,H,S,Dh]
__device__ float g_v  [(size_t)NROWS*DDIM];     // [B,H,S,Dh]
__device__ float g_ctx[(size_t)NROWS*DDIM];     // [B,S,D]
__device__ float g_msg[(size_t)NROWS*DDIM];     // [B,S,D]
__device__ float g_cat[(size_t)NROWS*512];      // [B*S, 512]
__device__ float g_x1 [(size_t)NROWS*512];      // [B*S, 512]

// ---------------- generic NT GEMM: C[M,N] = A[M,K] @ W[N,K]^T + bias -------
// tile 64x64, K-chunk 16, 256 threads, 4x4 microtile
__global__ void gemm_nt(const float* __restrict__ A, const float* __restrict__ W,
                        const float* __restrict__ bias, float* __restrict__ C,
                        int K) {
    __shared__ float As[64][17];
    __shared__ float Ws[64][17];
    int tid = threadIdx.x;
    int tx = tid & 15, ty = tid >> 4;
    int rowBase = blockIdx.y * 64;
    int colBase = blockIdx.x * 64;
    int N = gridDim.x * 64;
    float acc[4][4] = {};
    for (int k0 = 0; k0 < K; k0 += 16) {
        #pragma unroll
        for (int i = 0; i < 4; i++) {
            int e = tid + i*256;
            int r = e >> 4, c = e & 15;
            As[r][c] = A[(size_t)(rowBase+r)*K + k0 + c];
            Ws[r][c] = W[(size_t)(colBase+r)*K + k0 + c];
        }
        __syncthreads();
        #pragma unroll
        for (int kk = 0; kk < 16; kk++) {
            float a[4], w[4];
            #pragma unroll
            for (int i = 0; i < 4; i++) a[i] = As[ty*4+i][kk];
            #pragma unroll
            for (int j = 0; j < 4; j++) w[j] = Ws[tx*4+j][kk];
            #pragma unroll
            for (int i = 0; i < 4; i++)
                #pragma unroll
                for (int j = 0; j < 4; j++)
                    acc[i][j] += a[i]*w[j];
        }
        __syncthreads();
    }
    #pragma unroll
    for (int i = 0; i < 4; i++) {
        int row = rowBase + ty*4 + i;
        #pragma unroll
        for (int j = 0; j < 4; j++) {
            int col = colBase + tx*4 + j;
            C[(size_t)row*N + col] = acc[i][j] + bias[col];
        }
    }
}

// ---------------- rotary + split qkv into [B,H,S,Dh] -----------------------
// qkv last dim layout: j = h*192 + d*3 + c   (c: 0=q,1=k,2=v), rotary on d-pairs
__global__ void rotary_split(const float* __restrict__ kp) {
    int idx = blockIdx.x*blockDim.x + threadIdx.x;   // NROWS*H*32 threads
    int i   = idx & 31;          // pair index, d = 2i
    int h   = (idx >> 5) & 3;
    int row = idx >> 7;          // b*S + s
    const float* qkv = g_qkv + (size_t)row*768 + h*192 + i*6;
    float q0 = qkv[0], k0 = qkv[1], v0 = qkv[2];
    float q1 = qkv[3], k1 = qkv[4], v1 = qkv[5];
    int d = i*2;
    size_t co = (size_t)row*DH + d;
    float c0 = kp[co],                 c1 = kp[co+1];
    float s0 = kp[(size_t)BB*SS*DH + co], s1 = kp[(size_t)BB*SS*DH + co + 1];
    int b = row >> 11;      // /2048
    int s = row & 2047;
    size_t o = (((size_t)(b*HH + h))*SS + s)*DH + d;
    // x*cos + rotate_half(x)*sin ; rotate_half: (x0,x1)->(-x1,x0)
    g_q[o]   = q0*c0 - q1*s0;
    g_q[o+1] = q1*c1 + q0*s1;
    g_k[o]   = k0*c0 - k1*s0;
    g_k[o+1] = k1*c1 + k0*s1;
    g_v[o]   = v0;
    g_v[o+1] = v1;
}

// ---------------- flash attention: Br=64, Bc=32, online softmax ------------
__global__ void flash_attn() {
    __shared__ float Qs[64][65];
    __shared__ float Ks[32][65];
    __shared__ float Vs[32][65];
    __shared__ float Ps[64][33];
    int tid = threadIdx.x;
    int tx = tid & 15, ty = tid >> 4;
    int bh = blockIdx.y;                 // b*H + h
    int q0r = blockIdx.x * 64;
    size_t base = (size_t)bh * SS * DH;
    #pragma unroll
    for (int it = 0; it < 16; it++) {
        int e = tid + it*256;
        int r = e >> 6, c = e & 63;
        Qs[r][c] = g_q[base + (size_t)(q0r + r)*DH + c];
    }
    float m[4], l[4], O[4][4];
    #pragma unroll
    for (int i = 0; i < 4; i++) {
        m[i] = -1e30f; l[i] = 0.f;
        #pragma unroll
        for (int j = 0; j < 4; j++) O[i][j] = 0.f;
    }
    for (int kt = 0; kt < SS/32; kt++) {
        #pragma unroll
        for (int it = 0; it < 8; it++) {
            int e = tid + it*256;
            int r = e >> 6, c = e & 63;
            size_t g = base + (size_t)(kt*32 + r)*DH + c;
            Ks[r][c] = g_k[g];
            Vs[r][c] = g_v[g];
        }
        __syncthreads();
        float s[4][2] = {};
        #pragma unroll 8
        for (int kk = 0; kk < 64; kk++) {
            float a[4], bv[2];
            #pragma unroll
            for (int i = 0; i < 4; i++) a[i] = Qs[ty*4+i][kk];
            bv[0] = Ks[tx*2][kk]; bv[1] = Ks[tx*2+1][kk];
            #pragma unroll
            for (int i = 0; i < 4; i++) { s[i][0] += a[i]*bv[0]; s[i][1] += a[i]*bv[1]; }
        }
        #pragma unroll
        for (int i = 0; i < 4; i++) {
            float sm0 = s[i][0]*0.125f, sm1 = s[i][1]*0.125f;
            float tmax = fmaxf(sm0, sm1);
            #pragma unroll
            for (int o = 8; o >= 1; o >>= 1)
                tmax = fmaxf(tmax, __shfl_xor_sync(0xffffffffu, tmax, o));
            float mn = fmaxf(m[i], tmax);
            float alpha = __expf(m[i] - mn);
            float p0 = __expf(sm0 - mn), p1 = __expf(sm1 - mn);
            float ps = p0 + p1;
            #pragma unroll
            for (int o = 8; o >= 1; o >>= 1)
                ps += __shfl_xor_sync(0xffffffffu, ps, o);
            l[i] = l[i]*alpha + ps;
            m[i] = mn;
            #pragma unroll
            for (int j = 0; j < 4; j++) O[i][j] *= alpha;
            Ps[ty*4+i][tx*2]   = p0;
            Ps[ty*4+i][tx*2+1] = p1;
        }
        __syncthreads();
        #pragma unroll 8
        for (int kk = 0; kk < 32; kk++) {
            float p[4], v[4];
            #pragma unroll
            for (int i = 0; i < 4; i++) p[i] = Ps[ty*4+i][kk];
            #pragma unroll
            for (int j = 0; j < 4; j++) v[j] = Vs[kk][tx*4+j];
            #pragma unroll
            for (int i = 0; i < 4; i++)
                #pragma unroll
                for (int j = 0; j < 4; j++)
                    O[i][j] += p[i]*v[j];
        }
        __syncthreads();
    }
    int b = bh >> 2, h = bh & 3;
    #pragma unroll
    for (int i = 0; i < 4; i++) {
        float inv = 1.f / l[i];
        int srow = q0r + ty*4 + i;
        size_t o = ((size_t)(b*SS + srow))*DDIM + h*DH + tx*4;
        #pragma unroll
        for (int j = 0; j < 4; j++) g_ctx[o+j] = O[i][j]*inv;
    }
}

// ---------------- concat [desc | msg] -> g_cat ------------------------------
__global__ void concat_kernel(const float* __restrict__ desc) {
    int e = blockIdx.x*blockDim.x + threadIdx.x;   // NROWS*512 threads
    int r = e >> 9, c = e & 511;
    g_cat[e] = (c < 256) ? desc[(size_t)r*256 + c]
                         : g_msg[(size_t)r*256 + c - 256];
}

// ---------------- LayerNorm + exact GELU + W2 GEMM + residual ---------------
// 16 rows per block; LN per warp (2 rows/warp); then 16x256 tile GEMM vs W2[256,512]
__global__ void ln_gelu_w2(const float* __restrict__ desc,
                           const float* __restrict__ lng, const float* __restrict__ lnb,
                           const float* __restrict__ W2, const float* __restrict__ b2,
                           float* __restrict__ out) {
    __shared__ float xs[16][512];
    __shared__ float ws[256][9];
    int tid = threadIdx.x;
    int r0 = blockIdx.x * 16;
    #pragma unroll
    for (int it = 0; it < 32; it++) {
        int e = tid + it*256;
        int r = e >> 9, c = e & 511;
        xs[r][c] = g_x1[(size_t)(r0+r)*512 + c];
    }
    __syncthreads();
    int warp = tid >> 5, lane = tid & 31;
    #pragma unroll
    for (int rr = 0; rr < 2; rr++) {
        int r = warp*2 + rr;
        float s = 0.f, s2 = 0.f;
        #pragma unroll
        for (int c = lane; c < 512; c += 32) { float x = xs[r][c]; s += x; s2 += x*x; }
        #pragma unroll
        for (int o = 16; o >= 1; o >>= 1) {
            s  += __shfl_xor_sync(0xffffffffu, s,  o);
            s2 += __shfl_xor_sync(0xffffffffu, s2, o);
        }
        float mean = s * (1.f/512.f);
        float var  = s2 * (1.f/512.f) - mean*mean;
        float inv  = rsqrtf(var + 1e-5f);
        #pragma unroll
        for (int c = lane; c < 512; c += 32) {
            float y = (xs[r][c] - mean)*inv*lng[c] + lnb[c];
            xs[r][c] = 0.5f*y*(1.f + erff(y*0.7071067811865476f));
        }
    }
    __syncthreads();
    int tx2 = tid & 63, ty2 = tid >> 6;       // cols 4*tx2.. , rows 4*ty2..
    float acc[4][4] = {};
    for (int kc = 0; kc < 512; kc += 8) {
        #pragma unroll
        for (int it = 0; it < 8; it++) {
            int e = tid + it*256;
            int cr = e >> 3, cc = e & 7;
            ws[cr][cc] = W2[(size_t)cr*512 + kc + cc];
        }
        __syncthreads();
        #pragma unroll
        for (int kk = 0; kk < 8; kk++) {
            float a[4], w[4];
            #pragma unroll
            for (int i = 0; i < 4; i++) a[i] = xs[ty2*4+i][kc+kk];
            #pragma unroll
            for (int j = 0; j < 4; j++) w[j] = ws[tx2*4+j][kk];
            #pragma unroll
            for (int i = 0; i < 4; i++)
                #pragma unroll
                for (int j = 0; j < 4; j++)
                    acc[i][j] += a[i]*w[j];
        }
        __syncthreads();
    }
    #pragma unroll
    for (int i = 0; i < 4; i++) {
        int row = r0 + ty2*4 + i;
        #pragma unroll
        for (int j = 0; j < 4; j++) {
            int col = tx2*4 + j;
            out[(size_t)row*256 + col] = desc[(size_t)row*256 + col] + acc[i][j] + b2[col];
        }
    }
}

// ---------------------------------------------------------------------------
extern "C" void kernel_launch(void* const* d_in, const int* in_sizes, int n_in,
                              void* d_out, int out_size) {
    const float* desc   = (const float*)d_in[0];
    const float* kp     = (const float*)d_in[1];
    const float* Wqkv_w = (const float*)d_in[2];
    const float* Wqkv_b = (const float*)d_in[3];
    const float* Wo_w   = (const float*)d_in[4];
    const float* Wo_b   = (const float*)d_in[5];
    const float* W1_w   = (const float*)d_in[6];
    const float* W1_b   = (const float*)d_in[7];
    const float* lng    = (const float*)d_in[8];
    const float* lnb    = (const float*)d_in[9];
    const float* W2_w   = (const float*)d_in[10];
    const float* W2_b   = (const float*)d_in[11];
    float* out = (float*)d_out;

    void *p_qkv, *p_ctx, *p_msg, *p_cat, *p_x1;
    cudaGetSymbolAddress(&p_qkv, g_qkv);
    cudaGetSymbolAddress(&p_ctx, g_ctx);
    cudaGetSymbolAddress(&p_msg, g_msg);
    cudaGetSymbolAddress(&p_cat, g_cat);
    cudaGetSymbolAddress(&p_x1,  g_x1);

    // 1) qkv = desc @ Wqkv^T + b          [16384, 768]
    gemm_nt<<<dim3(12, 256), 256>>>(desc, Wqkv_w, Wqkv_b, (float*)p_qkv, 256);
    // 2) rotary + split to q/k/v [B,H,S,Dh]
    rotary_split<<<(NROWS*HH*32)/256, 256>>>(kp);
    // 3) flash attention -> ctx [B,S,D]
    flash_attn<<<dim3(SS/64, BB*HH), 256>>>();
    // 4) msg = ctx @ Wo^T + b             [16384, 256]
    gemm_nt<<<dim3(4, 256), 256>>>((const float*)p_ctx, Wo_w, Wo_b, (float*)p_msg, 256);
    // 5) cat = [desc | msg]               [16384, 512]
    concat_kernel<<<(NROWS*512)/256, 256>>>(desc);
    // 6) x1 = cat @ W1^T + b              [16384, 512]
    gemm_nt<<<dim3(8, 256), 256>>>((const float*)p_cat, W1_w, W1_b, (float*)p_x1, 512);
    // 7) LN + GELU + W2 + bias + residual -> out
    ln_gelu_w2<<<NROWS/16, 256>>>(desc, lng, lnb, W2_w, W2_b, out);
}

// round 4
// speedup vs baseline: 2.8641x; 2.8641x over previous
#include <cuda_runtime.h>
#include <math.h>

#define BB 8
#define SS 2048
#define DDIM 256
#define HH 4
#define DH 64
#define NROWS (BB*SS)   // 16384

// ---------------- scratch (static device allocations; no cudaMalloc) -------
__device__ float g_qkv[(size_t)NROWS*768];      // [B*S, 768] interleaved (h,d,3)
__device__ float g_q  [(size_t)NROWS*DDIM];     // [B,H,S,Dh]
__device__ float g_k  [(size_t)NROWS*DDIM];     // [B,H,S,Dh]
__device__ float g_v  [(size_t)NROWS*DDIM];     // [B,H,S,Dh]
__device__ float g_ctx[(size_t)NROWS*DDIM];     // [B,S,D]
__device__ float g_msg[(size_t)NROWS*DDIM];     // [B,S,D]
__device__ float g_x1 [(size_t)NROWS*512];      // [B*S, 512]

// ---------------- helpers ---------------------------------------------------
__device__ __forceinline__ unsigned f2tf(float x) {
    unsigned r;
    asm("cvt.rna.tf32.f32 %0, %1;" : "=r"(r) : "f"(x));
    return r;
}

__device__ __forceinline__ void mma8(float* d, const unsigned* a,
                                     unsigned b0, unsigned b1, const float* c) {
    asm volatile(
        "mma.sync.aligned.m16n8k8.row.col.f32.tf32.tf32.f32 "
        "{%0,%1,%2,%3}, {%4,%5,%6,%7}, {%8,%9}, {%10,%11,%12,%13};"
        : "=f"(d[0]), "=f"(d[1]), "=f"(d[2]), "=f"(d[3])
        : "r"(a[0]), "r"(a[1]), "r"(a[2]), "r"(a[3]), "r"(b0), "r"(b1),
          "f"(c[0]), "f"(c[1]), "f"(c[2]), "f"(c[3]));
}

// fast exp via exp2 polynomial (no MUFU). Valid for x <= 0 (softmax deltas).
__device__ __forceinline__ float fast_exp(float x) {
    float t = fmaxf(x * 1.4426950408889634f, -126.0f);
    int   i = __float2int_rd(t);
    float f = t - (float)i;
    float p = 1.33336498402e-3f;
    p = fmaf(p, f, 9.81094791730e-3f);
    p = fmaf(p, f, 5.54906055893e-2f);
    p = fmaf(p, f, 2.40226506959e-1f);
    p = fmaf(p, f, 6.93147180560e-1f);
    p = fmaf(p, f, 1.0f);
    return p * __int_as_float((i + 127) << 23);
}

// ---------------- tf32 tensor-core GEMM: C = A @ W^T + bias (+res) ---------
// A[M,K] logically split in K: cols < split from A0 (stride split), rest from
// A1 (stride K-split). W[N,K]. Block tile 128x64, 256 thr, warp tile 32x32.
__global__ void __launch_bounds__(256) gemm_tf32(
    const float* __restrict__ A0, const float* __restrict__ A1, int split,
    const float* __restrict__ W, const float* __restrict__ bias,
    const float* __restrict__ res, float* __restrict__ C, int K, int N)
{
    __shared__ unsigned As[128*20];
    __shared__ unsigned Ws[64*20];
    int tid = threadIdx.x;
    int wid = tid >> 5, lane = tid & 31;
    int g = lane >> 2, t = lane & 3;
    int wm = wid & 3, wn = wid >> 2;
    int rowBase = blockIdx.y * 128;
    int colBase = blockIdx.x * 64;
    int sA1 = K - split;
    float acc[2][4][4] = {};

    for (int k0 = 0; k0 < K; k0 += 16) {
        #pragma unroll
        for (int i = 0; i < 2; i++) {
            int e = tid + i*256;              // 0..511 float4 slots
            int r = e >> 2, c4 = (e & 3)*4;
            int kg = k0 + c4;
            const float* src = (kg < split)
                ? (A0 + (size_t)(rowBase+r)*split + kg)
                : (A1 + (size_t)(rowBase+r)*sA1 + (kg - split));
            float4 v = *(const float4*)src;
            uint4 u = make_uint4(f2tf(v.x), f2tf(v.y), f2tf(v.z), f2tf(v.w));
            *(uint4*)&As[r*20 + c4] = u;
        }
        {
            int r = tid >> 2, c4 = (tid & 3)*4;
            float4 v = *(const float4*)(W + (size_t)(colBase+r)*K + k0 + c4);
            uint4 u = make_uint4(f2tf(v.x), f2tf(v.y), f2tf(v.z), f2tf(v.w));
            *(uint4*)&Ws[r*20 + c4] = u;
        }
        __syncthreads();
        #pragma unroll
        for (int k8 = 0; k8 < 16; k8 += 8) {
            unsigned a[2][4], b[4][2];
            #pragma unroll
            for (int mi = 0; mi < 2; mi++) {
                int r = wm*32 + mi*16 + g;
                a[mi][0] = As[r*20 + k8 + t];
                a[mi][1] = As[(r+8)*20 + k8 + t];
                a[mi][2] = As[r*20 + k8 + t + 4];
                a[mi][3] = As[(r+8)*20 + k8 + t + 4];
            }
            #pragma unroll
            for (int ni = 0; ni < 4; ni++) {
                int c = wn*32 + ni*8 + g;
                b[ni][0] = Ws[c*20 + k8 + t];
                b[ni][1] = Ws[c*20 + k8 + t + 4];
            }
            #pragma unroll
            for (int mi = 0; mi < 2; mi++)
                #pragma unroll
                for (int ni = 0; ni < 4; ni++)
                    mma8(acc[mi][ni], a[mi], b[ni][0], b[ni][1], acc[mi][ni]);
        }
        __syncthreads();
    }

    #pragma unroll
    for (int mi = 0; mi < 2; mi++) {
        int r0 = rowBase + wm*32 + mi*16 + g;
        #pragma unroll
        for (int ni = 0; ni < 4; ni++) {
            int c = colBase + wn*32 + ni*8 + 2*t;
            float b0 = bias[c], b1 = bias[c+1];
            float v00 = acc[mi][ni][0] + b0, v01 = acc[mi][ni][1] + b1;
            float v10 = acc[mi][ni][2] + b0, v11 = acc[mi][ni][3] + b1;
            if (res) {
                v00 += res[(size_t)r0*N + c];     v01 += res[(size_t)r0*N + c + 1];
                v10 += res[(size_t)(r0+8)*N + c]; v11 += res[(size_t)(r0+8)*N + c + 1];
            }
            *(float2*)&C[(size_t)r0*N + c]     = make_float2(v00, v01);
            *(float2*)&C[(size_t)(r0+8)*N + c] = make_float2(v10, v11);
        }
    }
}

// ---------------- rotary + split qkv into [B,H,S,Dh] -----------------------
__global__ void rotary_split(const float* __restrict__ kp) {
    int idx = blockIdx.x*blockDim.x + threadIdx.x;
    int i   = idx & 31;
    int h   = (idx >> 5) & 3;
    int row = idx >> 7;
    const float* qkv = g_qkv + (size_t)row*768 + h*192 + i*6;
    float q0 = qkv[0], k0 = qkv[1], v0 = qkv[2];
    float q1 = qkv[3], k1 = qkv[4], v1 = qkv[5];
    int d = i*2;
    size_t co = (size_t)row*DH + d;
    float c0 = kp[co],                    c1 = kp[co+1];
    float s0 = kp[(size_t)BB*SS*DH + co], s1 = kp[(size_t)BB*SS*DH + co + 1];
    int b = row >> 11;
    int s = row & 2047;
    size_t o = (((size_t)(b*HH + h))*SS + s)*DH + d;
    g_q[o]   = q0*c0 - q1*s0;
    g_q[o+1] = q1*c1 + q0*s1;
    g_k[o]   = k0*c0 - k1*s0;
    g_k[o+1] = k1*c1 + k0*s1;
    g_v[o]   = v0;
    g_v[o+1] = v1;
}

// ---------------- flash attention, tf32 mma: Br=128, Bc=64 ------------------
// 256 thr = 8 warps, each warp owns 16 q-rows. smem stride 72 (conflict-free).
__global__ void __launch_bounds__(256, 2) flash_attn() {
    extern __shared__ unsigned sh[];
    unsigned* Qs = sh;               // [128][72]
    unsigned* Ks = Qs + 128*72;      // [64][72]  row=seq(n), col=d(k)
    unsigned* Vs = Ks + 64*72;       // [64][72]  row=seq(k), col=d(n)
    unsigned* Ps = Vs + 64*72;       // [128][72]
    int tid = threadIdx.x, wid = tid >> 5, lane = tid & 31;
    int g = lane >> 2, t = lane & 3;
    int bh = blockIdx.y;
    int q0 = blockIdx.x * 128;
    size_t base = (size_t)bh * SS * DH;

    #pragma unroll
    for (int i = 0; i < 8; i++) {
        int e = tid + i*256;
        int r = e >> 4, c4 = (e & 15)*4;
        float4 v = *(const float4*)(g_q + base + (size_t)(q0+r)*DH + c4);
        uint4 u = make_uint4(f2tf(v.x*0.125f), f2tf(v.y*0.125f),
                             f2tf(v.z*0.125f), f2tf(v.w*0.125f));
        *(uint4*)&Qs[r*72 + c4] = u;
    }

    float m0 = -1e30f, m1 = -1e30f, l0 = 0.f, l1 = 0.f;
    float o[8][4];
    #pragma unroll
    for (int n = 0; n < 8; n++)
        #pragma unroll
        for (int j = 0; j < 4; j++) o[n][j] = 0.f;
    int qrow = wid * 16;

    for (int kt = 0; kt < SS/64; kt++) {
        #pragma unroll
        for (int i = 0; i < 4; i++) {
            int e = tid + i*256;
            int r = e >> 4, c4 = (e & 15)*4;
            size_t gk = base + (size_t)(kt*64 + r)*DH + c4;
            float4 kv = *(const float4*)(g_k + gk);
            float4 vv = *(const float4*)(g_v + gk);
            *(uint4*)&Ks[r*72 + c4] = make_uint4(f2tf(kv.x), f2tf(kv.y), f2tf(kv.z), f2tf(kv.w));
            *(uint4*)&Vs[r*72 + c4] = make_uint4(f2tf(vv.x), f2tf(vv.y), f2tf(vv.z), f2tf(vv.w));
        }
        __syncthreads();

        // S = Q K^T  (pre-scaled)
        float sc[8][4] = {};
        #pragma unroll
        for (int k8 = 0; k8 < 64; k8 += 8) {
            unsigned a[4];
            a[0] = Qs[(qrow+g)*72 + k8 + t];
            a[1] = Qs[(qrow+g+8)*72 + k8 + t];
            a[2] = Qs[(qrow+g)*72 + k8 + t + 4];
            a[3] = Qs[(qrow+g+8)*72 + k8 + t + 4];
            #pragma unroll
            for (int n = 0; n < 8; n++) {
                unsigned b0 = Ks[(n*8+g)*72 + k8 + t];
                unsigned b1 = Ks[(n*8+g)*72 + k8 + t + 4];
                mma8(sc[n], a, b0, b1, sc[n]);
            }
        }

        // online softmax (rows qrow+g and qrow+g+8)
        float mx0 = -1e30f, mx1 = -1e30f;
        #pragma unroll
        for (int n = 0; n < 8; n++) {
            mx0 = fmaxf(mx0, fmaxf(sc[n][0], sc[n][1]));
            mx1 = fmaxf(mx1, fmaxf(sc[n][2], sc[n][3]));
        }
        #pragma unroll
        for (int off = 1; off <= 2; off <<= 1) {
            mx0 = fmaxf(mx0, __shfl_xor_sync(0xffffffffu, mx0, off));
            mx1 = fmaxf(mx1, __shfl_xor_sync(0xffffffffu, mx1, off));
        }
        float mn0 = fmaxf(m0, mx0), mn1 = fmaxf(m1, mx1);
        float al0 = fast_exp(m0 - mn0), al1 = fast_exp(m1 - mn1);
        m0 = mn0; m1 = mn1;
        float s0 = 0.f, s1 = 0.f;
        #pragma unroll
        for (int n = 0; n < 8; n++) {
            float p00 = fast_exp(sc[n][0] - m0);
            float p01 = fast_exp(sc[n][1] - m0);
            float p10 = fast_exp(sc[n][2] - m1);
            float p11 = fast_exp(sc[n][3] - m1);
            s0 += p00 + p01; s1 += p10 + p11;
            Ps[(qrow+g)*72 + n*8 + 2*t]     = f2tf(p00);
            Ps[(qrow+g)*72 + n*8 + 2*t + 1] = f2tf(p01);
            Ps[(qrow+g+8)*72 + n*8 + 2*t]     = f2tf(p10);
            Ps[(qrow+g+8)*72 + n*8 + 2*t + 1] = f2tf(p11);
        }
        #pragma unroll
        for (int off = 1; off <= 2; off <<= 1) {
            s0 += __shfl_xor_sync(0xffffffffu, s0, off);
            s1 += __shfl_xor_sync(0xffffffffu, s1, off);
        }
        l0 = l0*al0 + s0;
        l1 = l1*al1 + s1;
        #pragma unroll
        for (int n = 0; n < 8; n++) {
            o[n][0] *= al0; o[n][1] *= al0;
            o[n][2] *= al1; o[n][3] *= al1;
        }
        __syncwarp();

        // O += P V
        #pragma unroll
        for (int k8 = 0; k8 < 64; k8 += 8) {
            unsigned a[4];
            a[0] = Ps[(qrow+g)*72 + k8 + t];
            a[1] = Ps[(qrow+g+8)*72 + k8 + t];
            a[2] = Ps[(qrow+g)*72 + k8 + t + 4];
            a[3] = Ps[(qrow+g+8)*72 + k8 + t + 4];
            #pragma unroll
            for (int n = 0; n < 8; n++) {
                unsigned b0 = Vs[(k8+t)*72 + n*8 + g];
                unsigned b1 = Vs[(k8+t+4)*72 + n*8 + g];
                mma8(o[n], a, b0, b1, o[n]);
            }
        }
        __syncthreads();
    }

    float inv0 = 1.f / l0, inv1 = 1.f / l1;
    int b = bh >> 2, h = bh & 3;
    int r0 = q0 + qrow + g;
    #pragma unroll
    for (int n = 0; n < 8; n++) {
        int c = h*64 + n*8 + 2*t;
        *(float2*)&g_ctx[((size_t)(b*SS + r0))*DDIM + c] =
            make_float2(o[n][0]*inv0, o[n][1]*inv0);
        *(float2*)&g_ctx[((size_t)(b*SS + r0 + 8))*DDIM + c] =
            make_float2(o[n][2]*inv1, o[n][3]*inv1);
    }
}

// ---------------- LayerNorm + exact GELU, in place on g_x1 ------------------
// 1 warp per row; 8 rows per 256-thread block.
__global__ void ln_gelu(const float* __restrict__ lng, const float* __restrict__ lnb) {
    int row = blockIdx.x*8 + (threadIdx.x >> 5);
    int lane = threadIdx.x & 31;
    float* x = g_x1 + (size_t)row*512;
    float4 v[4];
    float s = 0.f, s2 = 0.f;
    #pragma unroll
    for (int j = 0; j < 4; j++) {
        v[j] = *(float4*)&x[4*(lane + 32*j)];
        s  += v[j].x + v[j].y + v[j].z + v[j].w;
        s2 += v[j].x*v[j].x + v[j].y*v[j].y + v[j].z*v[j].z + v[j].w*v[j].w;
    }
    #pragma unroll
    for (int off = 16; off >= 1; off >>= 1) {
        s  += __shfl_xor_sync(0xffffffffu, s,  off);
        s2 += __shfl_xor_sync(0xffffffffu, s2, off);
    }
    float mean = s * (1.f/512.f);
    float var  = s2 * (1.f/512.f) - mean*mean;
    float inv  = rsqrtf(var + 1e-5f);
    #pragma unroll
    for (int j = 0; j < 4; j++) {
        int c = 4*(lane + 32*j);
        float* pv = (float*)&v[j];
        #pragma unroll
        for (int q = 0; q < 4; q++) {
            float y = (pv[q] - mean)*inv*lng[c+q] + lnb[c+q];
            pv[q] = 0.5f*y*(1.f + erff(y*0.7071067811865476f));
        }
        *(float4*)&x[c] = v[j];
    }
}

// ---------------------------------------------------------------------------
extern "C" void kernel_launch(void* const* d_in, const int* in_sizes, int n_in,
                              void* d_out, int out_size) {
    const float* desc   = (const float*)d_in[0];
    const float* kp     = (const float*)d_in[1];
    const float* Wqkv_w = (const float*)d_in[2];
    const float* Wqkv_b = (const float*)d_in[3];
    const float* Wo_w   = (const float*)d_in[4];
    const float* Wo_b   = (const float*)d_in[5];
    const float* W1_w   = (const float*)d_in[6];
    const float* W1_b   = (const float*)d_in[7];
    const float* lng    = (const float*)d_in[8];
    const float* lnb    = (const float*)d_in[9];
    const float* W2_w   = (const float*)d_in[10];
    const float* W2_b   = (const float*)d_in[11];
    float* out = (float*)d_out;

    void *p_qkv, *p_ctx, *p_msg, *p_x1;
    cudaGetSymbolAddress(&p_qkv, g_qkv);
    cudaGetSymbolAddress(&p_ctx, g_ctx);
    cudaGetSymbolAddress(&p_msg, g_msg);
    cudaGetSymbolAddress(&p_x1,  g_x1);

    cudaFuncSetAttribute(flash_attn, cudaFuncAttributeMaxDynamicSharedMemorySize,
                         384*72*4);

    // 1) qkv = desc @ Wqkv^T + b           [16384, 768]
    gemm_tf32<<<dim3(12, 128), 256>>>(desc, desc, 256, Wqkv_w, Wqkv_b,
                                      nullptr, (float*)p_qkv, 256, 768);
    // 2) rotary + split -> q/k/v [B,H,S,Dh]
    rotary_split<<<(NROWS*HH*32)/256, 256>>>(kp);
    // 3) flash attention -> ctx [B,S,D]
    flash_attn<<<dim3(SS/128, BB*HH), 256, 384*72*4>>>();
    // 4) msg = ctx @ Wo^T + b              [16384, 256]
    gemm_tf32<<<dim3(4, 128), 256>>>((const float*)p_ctx, (const float*)p_ctx, 256,
                                     Wo_w, Wo_b, nullptr, (float*)p_msg, 256, 256);
    // 5) x1 = [desc|msg] @ W1^T + b        [16384, 512]  (concat fused into K)
    gemm_tf32<<<dim3(8, 128), 256>>>(desc, (const float*)p_msg, 256,
                                     W1_w, W1_b, nullptr, (float*)p_x1, 512, 512);
    // 6) LayerNorm + exact GELU in place
    ln_gelu<<<NROWS/8, 256>>>(lng, lnb);
    // 7) out = desc + x1 @ W2^T + b        [16384, 256]
    gemm_tf32<<<dim3(4, 128), 256>>>((const float*)p_x1, (const float*)p_x1, 512,
                                     W2_w, W2_b, desc, out, 512, 256);
}

// round 6
// speedup vs baseline: 3.5511x; 1.2398x over previous
#include <cuda_runtime.h>
#include <math.h>

#define BB 8
#define SS 2048
#define DDIM 256
#define HH 4
#define DH 64
#define NROWS (BB*SS)   // 16384

// ---------------- scratch (static device allocations; no cudaMalloc) -------
__device__ float g_qkv[(size_t)NROWS*768];      // [B*S, 768] interleaved (h,d,3)
__device__ float g_q  [(size_t)NROWS*DDIM];     // [B,H,S,Dh]
__device__ float g_k  [(size_t)NROWS*DDIM];     // [B,H,S,Dh]
__device__ float g_v  [(size_t)NROWS*DDIM];     // [B,H,S,Dh]
__device__ float g_ctx[(size_t)NROWS*DDIM];     // [B,S,D]
__device__ float g_msg[(size_t)NROWS*DDIM];     // [B,S,D]
__device__ float g_x1 [(size_t)NROWS*512];      // [B*S, 512]

// ---------------- helpers ---------------------------------------------------
__device__ __forceinline__ unsigned f2tf(float x) {
    unsigned r;
    asm("cvt.rna.tf32.f32 %0, %1;" : "=r"(r) : "f"(x));
    return r;
}

__device__ __forceinline__ void mma8(float* d, const unsigned* a,
                                     unsigned b0, unsigned b1, const float* c) {
    asm volatile(
        "mma.sync.aligned.m16n8k8.row.col.f32.tf32.tf32.f32 "
        "{%0,%1,%2,%3}, {%4,%5,%6,%7}, {%8,%9}, {%10,%11,%12,%13};"
        : "=f"(d[0]), "=f"(d[1]), "=f"(d[2]), "=f"(d[3])
        : "r"(a[0]), "r"(a[1]), "r"(a[2]), "r"(a[3]), "r"(b0), "r"(b1),
          "f"(c[0]), "f"(c[1]), "f"(c[2]), "f"(c[3]));
}

__device__ __forceinline__ void cp16(void* smem_dst, const void* gmem_src) {
    unsigned s = (unsigned)__cvta_generic_to_shared(smem_dst);
    asm volatile("cp.async.cg.shared.global [%0], [%1], 16;\n"
                 :: "r"(s), "l"(gmem_src));
}

// fast exp via exp2 polynomial (no MUFU). Valid for x <= 0 (softmax deltas).
__device__ __forceinline__ float fast_exp(float x) {
    float t = fmaxf(x * 1.4426950408889634f, -126.0f);
    int   i = __float2int_rd(t);
    float f = t - (float)i;
    float p = 1.33336498402e-3f;
    p = fmaf(p, f, 9.81094791730e-3f);
    p = fmaf(p, f, 5.54906055893e-2f);
    p = fmaf(p, f, 2.40226506959e-1f);
    p = fmaf(p, f, 6.93147180560e-1f);
    p = fmaf(p, f, 1.0f);
    return p * __int_as_float((i + 127) << 23);
}

// ---------------- tf32 GEMM, cp.async double-buffered ----------------------
// C[M,N] = A[M,K] @ W[N,K]^T + bias (+res). A split in K at `split` (A0/A1).
// Block tile 128x128, warp tile 64x32 (8 warps as 2x4), K-chunk 32.
// smem: 2 stages x (A 128x32 + W 128x32) fp32, XOR-swizzled 128B rows.
// Inputs fed to mma.tf32 as raw fp32 bits (HW truncation).
__global__ void __launch_bounds__(256) gemm_ca(
    const float* __restrict__ A0, const float* __restrict__ A1, int split,
    const float* __restrict__ W, const float* __restrict__ bias,
    const float* __restrict__ res, float* __restrict__ C, int K, int N)
{
    extern __shared__ float sm[];
    float* Asm = sm;           // [2][4096]
    float* Wsm = sm + 8192;    // [2][4096]
    int tid = threadIdx.x;
    int wid = tid >> 5, lane = tid & 31;
    int g = lane >> 2, t = lane & 3;
    int wm = wid & 1, wn = wid >> 1;          // 2 x 4 warp grid
    int rowBase = blockIdx.y * 128;
    int colBase = blockIdx.x * 128;
    int sA1 = K - split;
    int KT = K / 32;
    float acc[4][4][4] = {};

    // async copy of chunk kt into stage st
    auto copy_tiles = [&](int kt, int st) {
        int k0 = kt * 32;
        #pragma unroll
        for (int i = 0; i < 4; i++) {
            int e = tid + i*256;              // 0..1023
            int r = e >> 3, grp = e & 7;
            int kg = k0 + grp*4;
            const float* srcA = (kg < split)
                ? (A0 + (size_t)(rowBase+r)*split + kg)
                : (A1 + (size_t)(rowBase+r)*sA1 + (kg - split));
            cp16(&Asm[st*4096 + r*32 + ((grp ^ (r & 7)) << 2)], srcA);
            const float* srcW = W + (size_t)(colBase+r)*K + kg;
            cp16(&Wsm[st*4096 + r*32 + ((grp ^ (r & 7)) << 2)], srcW);
        }
    };

    copy_tiles(0, 0);
    asm volatile("cp.async.commit_group;\n");

    for (int kt = 0; kt < KT; kt++) {
        if (kt + 1 < KT) {
            copy_tiles(kt+1, (kt+1) & 1);
            asm volatile("cp.async.commit_group;\n");
            asm volatile("cp.async.wait_group 1;\n");
        } else {
            asm volatile("cp.async.wait_group 0;\n");
        }
        __syncthreads();
        const float* Ab = Asm + (kt & 1)*4096;
        const float* Wb = Wsm + (kt & 1)*4096;
        #pragma unroll
        for (int k8 = 0; k8 < 32; k8 += 8) {
            int sw1 = (((k8 >> 2)     ^ g) << 2) + t;   // rows here all have (r&7)==g
            int sw2 = ((((k8 >> 2)+1) ^ g) << 2) + t;
            unsigned a[4][4];
            #pragma unroll
            for (int mi = 0; mi < 4; mi++) {
                int r = wm*64 + mi*16 + g;
                a[mi][0] = __float_as_uint(Ab[r*32 + sw1]);
                a[mi][1] = __float_as_uint(Ab[(r+8)*32 + sw1]);
                a[mi][2] = __float_as_uint(Ab[r*32 + sw2]);
                a[mi][3] = __float_as_uint(Ab[(r+8)*32 + sw2]);
            }
            unsigned b[4][2];
            #pragma unroll
            for (int ni = 0; ni < 4; ni++) {
                int c = wn*32 + ni*8 + g;
                b[ni][0] = __float_as_uint(Wb[c*32 + sw1]);
                b[ni][1] = __float_as_uint(Wb[c*32 + sw2]);
            }
            #pragma unroll
            for (int mi = 0; mi < 4; mi++)
                #pragma unroll
                for (int ni = 0; ni < 4; ni++)
                    mma8(acc[mi][ni], a[mi], b[ni][0], b[ni][1], acc[mi][ni]);
        }
        __syncthreads();
    }

    #pragma unroll
    for (int mi = 0; mi < 4; mi++) {
        int r0 = rowBase + wm*64 + mi*16 + g;
        #pragma unroll
        for (int ni = 0; ni < 4; ni++) {
            int c = colBase + wn*32 + ni*8 + 2*t;
            float b0 = bias[c], b1 = bias[c+1];
            float v00 = acc[mi][ni][0] + b0, v01 = acc[mi][ni][1] + b1;
            float v10 = acc[mi][ni][2] + b0, v11 = acc[mi][ni][3] + b1;
            if (res) {
                v00 += res[(size_t)r0*N + c];     v01 += res[(size_t)r0*N + c + 1];
                v10 += res[(size_t)(r0+8)*N + c]; v11 += res[(size_t)(r0+8)*N + c + 1];
            }
            *(float2*)&C[(size_t)r0*N + c]     = make_float2(v00, v01);
            *(float2*)&C[(size_t)(r0+8)*N + c] = make_float2(v10, v11);
        }
    }
}

// ---------------- rotary + split qkv into [B,H,S,Dh] -----------------------
__global__ void rotary_split(const float* __restrict__ kp) {
    int idx = blockIdx.x*blockDim.x + threadIdx.x;
    int i   = idx & 31;
    int h   = (idx >> 5) & 3;
    int row = idx >> 7;
    const float* qkv = g_qkv + (size_t)row*768 + h*192 + i*6;
    float q0 = qkv[0], k0 = qkv[1], v0 = qkv[2];
    float q1 = qkv[3], k1 = qkv[4], v1 = qkv[5];
    int d = i*2;
    size_t co = (size_t)row*DH + d;
    float c0 = kp[co],                    c1 = kp[co+1];
    float s0 = kp[(size_t)BB*SS*DH + co], s1 = kp[(size_t)BB*SS*DH + co + 1];
    int b = row >> 11;
    int s = row & 2047;
    size_t o = (((size_t)(b*HH + h))*SS + s)*DH + d;
    g_q[o]   = q0*c0 - q1*s0;
    g_q[o+1] = q1*c1 + q0*s1;
    g_k[o]   = k0*c0 - k1*s0;
    g_k[o+1] = k1*c1 + k0*s1;
    g_v[o]   = v0;
    g_v[o+1] = v1;
}

// ---------------- flash attention, tf32 mma: Br=128, Bc=64 ------------------
// 256 thr = 8 warps, each warp owns 16 q-rows. smem stride 72 (conflict-free).
__global__ void __launch_bounds__(256, 2) flash_attn() {
    extern __shared__ unsigned sh[];
    unsigned* Qs = sh;               // [128][72]
    unsigned* Ks = Qs + 128*72;      // [64][72]  row=seq(n), col=d(k)
    unsigned* Vs = Ks + 64*72;       // [64][72]  row=seq(k), col=d(n)
    unsigned* Ps = Vs + 64*72;       // [128][72]
    int tid = threadIdx.x, wid = tid >> 5, lane = tid & 31;
    int g = lane >> 2, t = lane & 3;
    int bh = blockIdx.y;
    int q0 = blockIdx.x * 128;
    size_t base = (size_t)bh * SS * DH;

    #pragma unroll
    for (int i = 0; i < 8; i++) {
        int e = tid + i*256;
        int r = e >> 4, c4 = (e & 15)*4;
        float4 v = *(const float4*)(g_q + base + (size_t)(q0+r)*DH + c4);
        uint4 u = make_uint4(f2tf(v.x*0.125f), f2tf(v.y*0.125f),
                             f2tf(v.z*0.125f), f2tf(v.w*0.125f));
        *(uint4*)&Qs[r*72 + c4] = u;
    }

    float m0 = -1e30f, m1 = -1e30f, l0 = 0.f, l1 = 0.f;
    float o[8][4];
    #pragma unroll
    for (int n = 0; n < 8; n++)
        #pragma unroll
        for (int j = 0; j < 4; j++) o[n][j] = 0.f;
    int qrow = wid * 16;

    for (int kt = 0; kt < SS/64; kt++) {
        #pragma unroll
        for (int i = 0; i < 4; i++) {
            int e = tid + i*256;
            int r = e >> 4, c4 = (e & 15)*4;
            size_t gk = base + (size_t)(kt*64 + r)*DH + c4;
            float4 kv = *(const float4*)(g_k + gk);
            float4 vv = *(const float4*)(g_v + gk);
            *(uint4*)&Ks[r*72 + c4] = make_uint4(f2tf(kv.x), f2tf(kv.y), f2tf(kv.z), f2tf(kv.w));
            *(uint4*)&Vs[r*72 + c4] = make_uint4(f2tf(vv.x), f2tf(vv.y), f2tf(vv.z), f2tf(vv.w));
        }
        __syncthreads();

        // S = Q K^T  (pre-scaled)
        float sc[8][4] = {};
        #pragma unroll
        for (int k8 = 0; k8 < 64; k8 += 8) {
            unsigned a[4];
            a[0] = Qs[(qrow+g)*72 + k8 + t];
            a[1] = Qs[(qrow+g+8)*72 + k8 + t];
            a[2] = Qs[(qrow+g)*72 + k8 + t + 4];
            a[3] = Qs[(qrow+g+8)*72 + k8 + t + 4];
            #pragma unroll
            for (int n = 0; n < 8; n++) {
                unsigned b0 = Ks[(n*8+g)*72 + k8 + t];
                unsigned b1 = Ks[(n*8+g)*72 + k8 + t + 4];
                mma8(sc[n], a, b0, b1, sc[n]);
            }
        }

        // online softmax (rows qrow+g and qrow+g+8)
        float mx0 = -1e30f, mx1 = -1e30f;
        #pragma unroll
        for (int n = 0; n < 8; n++) {
            mx0 = fmaxf(mx0, fmaxf(sc[n][0], sc[n][1]));
            mx1 = fmaxf(mx1, fmaxf(sc[n][2], sc[n][3]));
        }
        #pragma unroll
        for (int off = 1; off <= 2; off <<= 1) {
            mx0 = fmaxf(mx0, __shfl_xor_sync(0xffffffffu, mx0, off));
            mx1 = fmaxf(mx1, __shfl_xor_sync(0xffffffffu, mx1, off));
        }
        float mn0 = fmaxf(m0, mx0), mn1 = fmaxf(m1, mx1);
        float al0 = fast_exp(m0 - mn0), al1 = fast_exp(m1 - mn1);
        m0 = mn0; m1 = mn1;
        float s0 = 0.f, s1 = 0.f;
        #pragma unroll
        for (int n = 0; n < 8; n++) {
            float p00 = fast_exp(sc[n][0] - m0);
            float p01 = fast_exp(sc[n][1] - m0);
            float p10 = fast_exp(sc[n][2] - m1);
            float p11 = fast_exp(sc[n][3] - m1);
            s0 += p00 + p01; s1 += p10 + p11;
            Ps[(qrow+g)*72 + n*8 + 2*t]     = f2tf(p00);
            Ps[(qrow+g)*72 + n*8 + 2*t + 1] = f2tf(p01);
            Ps[(qrow+g+8)*72 + n*8 + 2*t]     = f2tf(p10);
            Ps[(qrow+g+8)*72 + n*8 + 2*t + 1] = f2tf(p11);
        }
        #pragma unroll
        for (int off = 1; off <= 2; off <<= 1) {
            s0 += __shfl_xor_sync(0xffffffffu, s0, off);
            s1 += __shfl_xor_sync(0xffffffffu, s1, off);
        }
        l0 = l0*al0 + s0;
        l1 = l1*al1 + s1;
        #pragma unroll
        for (int n = 0; n < 8; n++) {
            o[n][0] *= al0; o[n][1] *= al0;
            o[n][2] *= al1; o[n][3] *= al1;
        }
        __syncwarp();

        // O += P V
        #pragma unroll
        for (int k8 = 0; k8 < 64; k8 += 8) {
            unsigned a[4];
            a[0] = Ps[(qrow+g)*72 + k8 + t];
            a[1] = Ps[(qrow+g+8)*72 + k8 + t];
            a[2] = Ps[(qrow+g)*72 + k8 + t + 4];
            a[3] = Ps[(qrow+g+8)*72 + k8 + t + 4];
            #pragma unroll
            for (int n = 0; n < 8; n++) {
                unsigned b0 = Vs[(k8+t)*72 + n*8 + g];
                unsigned b1 = Vs[(k8+t+4)*72 + n*8 + g];
                mma8(o[n], a, b0, b1, o[n]);
            }
        }
        __syncthreads();
    }

    float inv0 = 1.f / l0, inv1 = 1.f / l1;
    int b = bh >> 2, h = bh & 3;
    int r0 = q0 + qrow + g;
    #pragma unroll
    for (int n = 0; n < 8; n++) {
        int c = h*64 + n*8 + 2*t;
        *(float2*)&g_ctx[((size_t)(b*SS + r0))*DDIM + c] =
            make_float2(o[n][0]*inv0, o[n][1]*inv0);
        *(float2*)&g_ctx[((size_t)(b*SS + r0 + 8))*DDIM + c] =
            make_float2(o[n][2]*inv1, o[n][3]*inv1);
    }
}

// ---------------- LayerNorm + exact GELU, in place on g_x1 ------------------
__global__ void ln_gelu(const float* __restrict__ lng, const float* __restrict__ lnb) {
    int row = blockIdx.x*8 + (threadIdx.x >> 5);
    int lane = threadIdx.x & 31;
    float* x = g_x1 + (size_t)row*512;
    float4 v[4];
    float s = 0.f, s2 = 0.f;
    #pragma unroll
    for (int j = 0; j < 4; j++) {
        v[j] = *(float4*)&x[4*(lane + 32*j)];
        s  += v[j].x + v[j].y + v[j].z + v[j].w;
        s2 += v[j].x*v[j].x + v[j].y*v[j].y + v[j].z*v[j].z + v[j].w*v[j].w;
    }
    #pragma unroll
    for (int off = 16; off >= 1; off >>= 1) {
        s  += __shfl_xor_sync(0xffffffffu, s,  off);
        s2 += __shfl_xor_sync(0xffffffffu, s2, off);
    }
    float mean = s * (1.f/512.f);
    float var  = s2 * (1.f/512.f) - mean*mean;
    float inv  = rsqrtf(var + 1e-5f);
    #pragma unroll
    for (int j = 0; j < 4; j++) {
        int c = 4*(lane + 32*j);
        float* pv = (float*)&v[j];
        #pragma unroll
        for (int q = 0; q < 4; q++) {
            float y = (pv[q] - mean)*inv*lng[c+q] + lnb[c+q];
            pv[q] = 0.5f*y*(1.f + erff(y*0.7071067811865476f));
        }
        *(float4*)&x[c] = v[j];
    }
}

// ---------------------------------------------------------------------------
extern "C" void kernel_launch(void* const* d_in, const int* in_sizes, int n_in,
                              void* d_out, int out_size) {
    const float* desc   = (const float*)d_in[0];
    const float* kp     = (const float*)d_in[1];
    const float* Wqkv_w = (const float*)d_in[2];
    const float* Wqkv_b = (const float*)d_in[3];
    const float* Wo_w   = (const float*)d_in[4];
    const float* Wo_b   = (const float*)d_in[5];
    const float* W1_w   = (const float*)d_in[6];
    const float* W1_b   = (const float*)d_in[7];
    const float* lng    = (const float*)d_in[8];
    const float* lnb    = (const float*)d_in[9];
    const float* W2_w   = (const float*)d_in[10];
    const float* W2_b   = (const float*)d_in[11];
    float* out = (float*)d_out;

    void *p_qkv, *p_ctx, *p_msg, *p_x1;
    cudaGetSymbolAddress(&p_qkv, g_qkv);
    cudaGetSymbolAddress(&p_ctx, g_ctx);
    cudaGetSymbolAddress(&p_msg, g_msg);
    cudaGetSymbolAddress(&p_x1,  g_x1);

    cudaFuncSetAttribute(flash_attn, cudaFuncAttributeMaxDynamicSharedMemorySize,
                         384*72*4);
    cudaFuncSetAttribute(gemm_ca, cudaFuncAttributeMaxDynamicSharedMemorySize,
                         65536);

    // 1) qkv = desc @ Wqkv^T + b           [16384, 768]
    gemm_ca<<<dim3(6, 128), 256, 65536>>>(desc, desc, 256, Wqkv_w, Wqkv_b,
                                          nullptr, (float*)p_qkv, 256, 768);
    // 2) rotary + split -> q/k/v [B,H,S,Dh]
    rotary_split<<<(NROWS*HH*32)/256, 256>>>(kp);
    // 3) flash attention -> ctx [B,S,D]
    flash_attn<<<dim3(SS/128, BB*HH), 256, 384*72*4>>>();
    // 4) msg = ctx @ Wo^T + b              [16384, 256]
    gemm_ca<<<dim3(2, 128), 256, 65536>>>((const float*)p_ctx, (const float*)p_ctx, 256,
                                          Wo_w, Wo_b, nullptr, (float*)p_msg, 256, 256);
    // 5) x1 = [desc|msg] @ W1^T + b        [16384, 512]  (concat fused into K)
    gemm_ca<<<dim3(4, 128), 256, 65536>>>(desc, (const float*)p_msg, 256,
                                          W1_w, W1_b, nullptr, (float*)p_x1, 512, 512);
    // 6) LayerNorm + exact GELU in place
    ln_gelu<<<NROWS/8, 256>>>(lng, lnb);
    // 7) out = desc + x1 @ W2^T + b        [16384, 256]
    gemm_ca<<<dim3(2, 128), 256, 65536>>>((const float*)p_x1, (const float*)p_x1, 512,
                                          W2_w, W2_b, desc, out, 512, 256);
}

// round 8
// speedup vs baseline: 3.5647x; 1.0038x over previous
#include <cuda_runtime.h>
#include <math.h>

#define BB 8
#define SS 2048
#define DDIM 256
#define HH 4
#define DH 64
#define NROWS (BB*SS)   // 16384

// ---------------- scratch (static device allocations; no cudaMalloc) -------
__device__ float g_qkv[(size_t)NROWS*768];      // [B*S, 768] interleaved (h,d,3)
__device__ float g_q  [(size_t)NROWS*DDIM];     // [B,H,S,Dh]
__device__ float g_k  [(size_t)NROWS*DDIM];     // [B,H,S,Dh]
__device__ float g_v  [(size_t)NROWS*DDIM];     // [B,H,S,Dh]
__device__ float g_ctx[(size_t)NROWS*DDIM];     // [B,S,D]
__device__ float g_msg[(size_t)NROWS*DDIM];     // [B,S,D]
__device__ float g_x1 [(size_t)NROWS*512];      // [B*S, 512]

// ---------------- helpers ---------------------------------------------------
__device__ __forceinline__ void mma8(float* d, const unsigned* a,
                                     unsigned b0, unsigned b1, const float* c) {
    asm volatile(
        "mma.sync.aligned.m16n8k8.row.col.f32.tf32.tf32.f32 "
        "{%0,%1,%2,%3}, {%4,%5,%6,%7}, {%8,%9}, {%10,%11,%12,%13};"
        : "=f"(d[0]), "=f"(d[1]), "=f"(d[2]), "=f"(d[3])
        : "r"(a[0]), "r"(a[1]), "r"(a[2]), "r"(a[3]), "r"(b0), "r"(b1),
          "f"(c[0]), "f"(c[1]), "f"(c[2]), "f"(c[3]));
}

__device__ __forceinline__ void cp16(void* smem_dst, const void* gmem_src) {
    unsigned s = (unsigned)__cvta_generic_to_shared(smem_dst);
    asm volatile("cp.async.cg.shared.global [%0], [%1], 16;\n"
                 :: "r"(s), "l"(gmem_src));
}

// exp(0.125*x) via exp2 polynomial (no MUFU). Valid for x <= 0.
// scale 0.125 folded into the log2(e) constant.
__device__ __forceinline__ float fast_exp_s(float x) {
    float t = fmaxf(x * 0.18033688011112043f, -126.0f);
    int   i = __float2int_rd(t);
    float f = t - (float)i;
    float p = 1.33336498402e-3f;
    p = fmaf(p, f, 9.81094791730e-3f);
    p = fmaf(p, f, 5.54906055893e-2f);
    p = fmaf(p, f, 2.40226506959e-1f);
    p = fmaf(p, f, 6.93147180560e-1f);
    p = fmaf(p, f, 1.0f);
    return p * __int_as_float((i + 127) << 23);
}

// ---------------- tf32 GEMM, cp.async double-buffered ----------------------
// C[M,N] = A[M,K] @ W[N,K]^T + bias (+res). A split in K at `split` (A0/A1).
// Block tile 128x128, warp tile 64x32 (8 warps as 2x4), K-chunk 32.
__global__ void __launch_bounds__(256) gemm_ca(
    const float* __restrict__ A0, const float* __restrict__ A1, int split,
    const float* __restrict__ W, const float* __restrict__ bias,
    const float* __restrict__ res, float* __restrict__ C, int K, int N)
{
    extern __shared__ float sm[];
    float* Asm = sm;           // [2][4096]
    float* Wsm = sm + 8192;    // [2][4096]
    int tid = threadIdx.x;
    int wid = tid >> 5, lane = tid & 31;
    int g = lane >> 2, t = lane & 3;
    int wm = wid & 1, wn = wid >> 1;          // 2 x 4 warp grid
    int rowBase = blockIdx.y * 128;
    int colBase = blockIdx.x * 128;
    int sA1 = K - split;
    int KT = K / 32;
    float acc[4][4][4] = {};

    auto copy_tiles = [&](int kt, int st) {
        int k0 = kt * 32;
        #pragma unroll
        for (int i = 0; i < 4; i++) {
            int e = tid + i*256;              // 0..1023
            int r = e >> 3, grp = e & 7;
            int kg = k0 + grp*4;
            const float* srcA = (kg < split)
                ? (A0 + (size_t)(rowBase+r)*split + kg)
                : (A1 + (size_t)(rowBase+r)*sA1 + (kg - split));
            cp16(&Asm[st*4096 + r*32 + ((grp ^ (r & 7)) << 2)], srcA);
            const float* srcW = W + (size_t)(colBase+r)*K + kg;
            cp16(&Wsm[st*4096 + r*32 + ((grp ^ (r & 7)) << 2)], srcW);
        }
    };

    copy_tiles(0, 0);
    asm volatile("cp.async.commit_group;\n");

    for (int kt = 0; kt < KT; kt++) {
        if (kt + 1 < KT) {
            copy_tiles(kt+1, (kt+1) & 1);
            asm volatile("cp.async.commit_group;\n");
            asm volatile("cp.async.wait_group 1;\n");
        } else {
            asm volatile("cp.async.wait_group 0;\n");
        }
        __syncthreads();
        const float* Ab = Asm + (kt & 1)*4096;
        const float* Wb = Wsm + (kt & 1)*4096;
        #pragma unroll
        for (int k8 = 0; k8 < 32; k8 += 8) {
            int sw1 = (((k8 >> 2)     ^ g) << 2) + t;
            int sw2 = ((((k8 >> 2)+1) ^ g) << 2) + t;
            unsigned a[4][4];
            #pragma unroll
            for (int mi = 0; mi < 4; mi++) {
                int r = wm*64 + mi*16 + g;
                a[mi][0] = __float_as_uint(Ab[r*32 + sw1]);
                a[mi][1] = __float_as_uint(Ab[(r+8)*32 + sw1]);
                a[mi][2] = __float_as_uint(Ab[r*32 + sw2]);
                a[mi][3] = __float_as_uint(Ab[(r+8)*32 + sw2]);
            }
            unsigned b[4][2];
            #pragma unroll
            for (int ni = 0; ni < 4; ni++) {
                int c = wn*32 + ni*8 + g;
                b[ni][0] = __float_as_uint(Wb[c*32 + sw1]);
                b[ni][1] = __float_as_uint(Wb[c*32 + sw2]);
            }
            #pragma unroll
            for (int mi = 0; mi < 4; mi++)
                #pragma unroll
                for (int ni = 0; ni < 4; ni++)
                    mma8(acc[mi][ni], a[mi], b[ni][0], b[ni][1], acc[mi][ni]);
        }
        __syncthreads();
    }

    #pragma unroll
    for (int mi = 0; mi < 4; mi++) {
        int r0 = rowBase + wm*64 + mi*16 + g;
        #pragma unroll
        for (int ni = 0; ni < 4; ni++) {
            int c = colBase + wn*32 + ni*8 + 2*t;
            float b0 = bias[c], b1 = bias[c+1];
            float v00 = acc[mi][ni][0] + b0, v01 = acc[mi][ni][1] + b1;
            float v10 = acc[mi][ni][2] + b0, v11 = acc[mi][ni][3] + b1;
            if (res) {
                v00 += res[(size_t)r0*N + c];     v01 += res[(size_t)r0*N + c + 1];
                v10 += res[(size_t)(r0+8)*N + c]; v11 += res[(size_t)(r0+8)*N + c + 1];
            }
            *(float2*)&C[(size_t)r0*N + c]     = make_float2(v00, v01);
            *(float2*)&C[(size_t)(r0+8)*N + c] = make_float2(v10, v11);
        }
    }
}

// ---------------- rotary + split qkv into [B,H,S,Dh] -----------------------
__global__ void rotary_split(const float* __restrict__ kp) {
    int idx = blockIdx.x*blockDim.x + threadIdx.x;
    int i   = idx & 31;
    int h   = (idx >> 5) & 3;
    int row = idx >> 7;
    const float* qkv = g_qkv + (size_t)row*768 + h*192 + i*6;
    float q0 = qkv[0], k0 = qkv[1], v0 = qkv[2];
    float q1 = qkv[3], k1 = qkv[4], v1 = qkv[5];
    int d = i*2;
    size_t co = (size_t)row*DH + d;
    float c0 = kp[co],                    c1 = kp[co+1];
    float s0 = kp[(size_t)BB*SS*DH + co], s1 = kp[(size_t)BB*SS*DH + co + 1];
    int b = row >> 11;
    int s = row & 2047;
    size_t o = (((size_t)(b*HH + h))*SS + s)*DH + d;
    g_q[o]   = q0*c0 - q1*s0;
    g_q[o+1] = q1*c1 + q0*s1;
    g_k[o]   = k0*c0 - k1*s0;
    g_k[o+1] = k1*c1 + k0*s1;
    g_v[o]   = v0;
    g_v[o+1] = v1;
}

// ---------------- flash attention, tf32 mma, cp.async pipelined -------------
// Br=128, Bc=64, 8 warps x 16 q-rows. Raw fp32 bits into mma (HW truncation);
// softmax scale folded into exp2 constant. K/V double-buffered via cp.async.
// smem floats: Q[128*72] | K[2][64*72] | V[2][64*72] | P[128*72] = 36864 (147KB)
__global__ void __launch_bounds__(256, 1) flash_attn() {
    extern __shared__ float sh[];
    float* Qs = sh;                        // [128][72]
    float* Ks = sh + 9216;                 // [2][64][72]
    float* Vs = sh + 18432;                // [2][64][72]
    float* Ps = sh + 27648;                // [128][72]
    int tid = threadIdx.x, wid = tid >> 5, lane = tid & 31;
    int g = lane >> 2, t = lane & 3;
    int bh = blockIdx.y;
    int q0 = blockIdx.x * 128;
    size_t base = (size_t)bh * SS * DH;

    auto copy_kv = [&](int kt, int st) {
        #pragma unroll
        for (int i = 0; i < 4; i++) {
            int e = tid + i*256;           // 0..1023
            int r = e >> 4, c4 = (e & 15)*4;
            size_t gk = base + (size_t)(kt*64 + r)*DH + c4;
            cp16(&Ks[st*4608 + r*72 + c4], g_k + gk);
            cp16(&Vs[st*4608 + r*72 + c4], g_v + gk);
        }
    };

    // prologue: Q tile + first K/V tile in one cp.async group
    #pragma unroll
    for (int i = 0; i < 8; i++) {
        int e = tid + i*256;               // 0..2047
        int r = e >> 4, c4 = (e & 15)*4;
        cp16(&Qs[r*72 + c4], g_q + base + (size_t)(q0 + r)*DH + c4);
    }
    copy_kv(0, 0);
    asm volatile("cp.async.commit_group;\n");

    float m0 = -1e30f, m1 = -1e30f, l0 = 0.f, l1 = 0.f;
    float o[8][4];
    #pragma unroll
    for (int n = 0; n < 8; n++)
        #pragma unroll
        for (int j = 0; j < 4; j++) o[n][j] = 0.f;
    int qrow = wid * 16;

    for (int kt = 0; kt < SS/64; kt++) {
        if (kt + 1 < SS/64) {
            copy_kv(kt+1, (kt+1) & 1);
            asm volatile("cp.async.commit_group;\n");
            asm volatile("cp.async.wait_group 1;\n");
        } else {
            asm volatile("cp.async.wait_group 0;\n");
        }
        __syncthreads();
        const float* Kb = Ks + (kt & 1)*4608;
        const float* Vb = Vs + (kt & 1)*4608;

        // S = Q K^T (raw logits; scale folded into exp)
        float sc[8][4] = {};
        #pragma unroll
        for (int k8 = 0; k8 < 64; k8 += 8) {
            unsigned a[4];
            a[0] = __float_as_uint(Qs[(qrow+g)*72 + k8 + t]);
            a[1] = __float_as_uint(Qs[(qrow+g+8)*72 + k8 + t]);
            a[2] = __float_as_uint(Qs[(qrow+g)*72 + k8 + t + 4]);
            a[3] = __float_as_uint(Qs[(qrow+g+8)*72 + k8 + t + 4]);
            #pragma unroll
            for (int n = 0; n < 8; n++) {
                unsigned b0 = __float_as_uint(Kb[(n*8+g)*72 + k8 + t]);
                unsigned b1 = __float_as_uint(Kb[(n*8+g)*72 + k8 + t + 4]);
                mma8(sc[n], a, b0, b1, sc[n]);
            }
        }

        // online softmax (rows qrow+g and qrow+g+8)
        float mx0 = -1e30f, mx1 = -1e30f;
        #pragma unroll
        for (int n = 0; n < 8; n++) {
            mx0 = fmaxf(mx0, fmaxf(sc[n][0], sc[n][1]));
            mx1 = fmaxf(mx1, fmaxf(sc[n][2], sc[n][3]));
        }
        #pragma unroll
        for (int off = 1; off <= 2; off <<= 1) {
            mx0 = fmaxf(mx0, __shfl_xor_sync(0xffffffffu, mx0, off));
            mx1 = fmaxf(mx1, __shfl_xor_sync(0xffffffffu, mx1, off));
        }
        float mn0 = fmaxf(m0, mx0), mn1 = fmaxf(m1, mx1);
        float al0 = fast_exp_s(m0 - mn0), al1 = fast_exp_s(m1 - mn1);
        m0 = mn0; m1 = mn1;
        float s0 = 0.f, s1 = 0.f;
        #pragma unroll
        for (int n = 0; n < 8; n++) {
            float p00 = fast_exp_s(sc[n][0] - m0);
            float p01 = fast_exp_s(sc[n][1] - m0);
            float p10 = fast_exp_s(sc[n][2] - m1);
            float p11 = fast_exp_s(sc[n][3] - m1);
            s0 += p00 + p01; s1 += p10 + p11;
            Ps[(qrow+g)*72 + n*8 + 2*t]       = p00;
            Ps[(qrow+g)*72 + n*8 + 2*t + 1]   = p01;
            Ps[(qrow+g+8)*72 + n*8 + 2*t]     = p10;
            Ps[(qrow+g+8)*72 + n*8 + 2*t + 1] = p11;
        }
        #pragma unroll
        for (int off = 1; off <= 2; off <<= 1) {
            s0 += __shfl_xor_sync(0xffffffffu, s0, off);
            s1 += __shfl_xor_sync(0xffffffffu, s1, off);
        }
        l0 = l0*al0 + s0;
        l1 = l1*al1 + s1;
        #pragma unroll
        for (int n = 0; n < 8; n++) {
            o[n][0] *= al0; o[n][1] *= al0;
            o[n][2] *= al1; o[n][3] *= al1;
        }
        __syncwarp();

        // O += P V
        #pragma unroll
        for (int k8 = 0; k8 < 64; k8 += 8) {
            unsigned a[4];
            a[0] = __float_as_uint(Ps[(qrow+g)*72 + k8 + t]);
            a[1] = __float_as_uint(Ps[(qrow+g+8)*72 + k8 + t]);
            a[2] = __float_as_uint(Ps[(qrow+g)*72 + k8 + t + 4]);
            a[3] = __float_as_uint(Ps[(qrow+g+8)*72 + k8 + t + 4]);
            #pragma unroll
            for (int n = 0; n < 8; n++) {
                unsigned b0 = __float_as_uint(Vb[(k8+t)*72 + n*8 + g]);
                unsigned b1 = __float_as_uint(Vb[(k8+t+4)*72 + n*8 + g]);
                mma8(o[n], a, b0, b1, o[n]);
            }
        }
        __syncthreads();
    }

    float inv0 = 1.f / l0, inv1 = 1.f / l1;
    int b = bh >> 2, h = bh & 3;
    int r0 = q0 + qrow + g;
    #pragma unroll
    for (int n = 0; n < 8; n++) {
        int c = h*64 + n*8 + 2*t;
        *(float2*)&g_ctx[((size_t)(b*SS + r0))*DDIM + c] =
            make_float2(o[n][0]*inv0, o[n][1]*inv0);
        *(float2*)&g_ctx[((size_t)(b*SS + r0 + 8))*DDIM + c] =
            make_float2(o[n][2]*inv1, o[n][3]*inv1);
    }
}

// ---------------- LayerNorm + exact GELU, in place on g_x1 ------------------
__global__ void ln_gelu(const float* __restrict__ lng, const float* __restrict__ lnb) {
    int row = blockIdx.x*8 + (threadIdx.x >> 5);
    int lane = threadIdx.x & 31;
    float* x = g_x1 + (size_t)row*512;
    float4 v[4];
    float s = 0.f, s2 = 0.f;
    #pragma unroll
    for (int j = 0; j < 4; j++) {
        v[j] = *(float4*)&x[4*(lane + 32*j)];
        s  += v[j].x + v[j].y + v[j].z + v[j].w;
        s2 += v[j].x*v[j].x + v[j].y*v[j].y + v[j].z*v[j].z + v[j].w*v[j].w;
    }
    #pragma unroll
    for (int off = 16; off >= 1; off >>= 1) {
        s  += __shfl_xor_sync(0xffffffffu, s,  off);
        s2 += __shfl_xor_sync(0xffffffffu, s2, off);
    }
    float mean = s * (1.f/512.f);
    float var  = s2 * (1.f/512.f) - mean*mean;
    float inv  = rsqrtf(var + 1e-5f);
    #pragma unroll
    for (int j = 0; j < 4; j++) {
        int c = 4*(lane + 32*j);
        float* pv = (float*)&v[j];
        #pragma unroll
        for (int q = 0; q < 4; q++) {
            float y = (pv[q] - mean)*inv*lng[c+q] + lnb[c+q];
            pv[q] = 0.5f*y*(1.f + erff(y*0.7071067811865476f));
        }
        *(float4*)&x[c] = v[j];
    }
}

// ---------------------------------------------------------------------------
extern "C" void kernel_launch(void* const* d_in, const int* in_sizes, int n_in,
                              void* d_out, int out_size) {
    const float* desc   = (const float*)d_in[0];
    const float* kp     = (const float*)d_in[1];
    const float* Wqkv_w = (const float*)d_in[2];
    const float* Wqkv_b = (const float*)d_in[3];
    const float* Wo_w   = (const float*)d_in[4];
    const float* Wo_b   = (const float*)d_in[5];
    const float* W1_w   = (const float*)d_in[6];
    const float* W1_b   = (const float*)d_in[7];
    const float* lng    = (const float*)d_in[8];
    const float* lnb    = (const float*)d_in[9];
    const float* W2_w   = (const float*)d_in[10];
    const float* W2_b   = (const float*)d_in[11];
    float* out = (float*)d_out;

    void *p_qkv, *p_ctx, *p_msg, *p_x1;
    cudaGetSymbolAddress(&p_qkv, g_qkv);
    cudaGetSymbolAddress(&p_ctx, g_ctx);
    cudaGetSymbolAddress(&p_msg, g_msg);
    cudaGetSymbolAddress(&p_x1,  g_x1);

    cudaFuncSetAttribute(flash_attn, cudaFuncAttributeMaxDynamicSharedMemorySize,
                         36864*4);
    cudaFuncSetAttribute(gemm_ca, cudaFuncAttributeMaxDynamicSharedMemorySize,
                         65536);

    // 1) qkv = desc @ Wqkv^T + b           [16384, 768]
    gemm_ca<<<dim3(6, 128), 256, 65536>>>(desc, desc, 256, Wqkv_w, Wqkv_b,
                                          nullptr, (float*)p_qkv, 256, 768);
    // 2) rotary + split -> q/k/v [B,H,S,Dh]
    rotary_split<<<(NROWS*HH*32)/256, 256>>>(kp);
    // 3) flash attention -> ctx [B,S,D]
    flash_attn<<<dim3(SS/128, BB*HH), 256, 36864*4>>>();
    // 4) msg = ctx @ Wo^T + b              [16384, 256]
    gemm_ca<<<dim3(2, 128), 256, 65536>>>((const float*)p_ctx, (const float*)p_ctx, 256,
                                          Wo_w, Wo_b, nullptr, (float*)p_msg, 256, 256);
    // 5) x1 = [desc|msg] @ W1^T + b        [16384, 512]  (concat fused into K)
    gemm_ca<<<dim3(4, 128), 256, 65536>>>(desc, (const float*)p_msg, 256,
                                          W1_w, W1_b, nullptr, (float*)p_x1, 512, 512);
    // 6) LayerNorm + exact GELU in place
    ln_gelu<<<NROWS/8, 256>>>(lng, lnb);
    // 7) out = desc + x1 @ W2^T + b        [16384, 256]
    gemm_ca<<<dim3(2, 128), 256, 65536>>>((const float*)p_x1, (const float*)p_x1, 512,
                                          W2_w, W2_b, desc, out, 512, 256);
}

// round 9
// speedup vs baseline: 3.9759x; 1.1154x over previous
#include <cuda_runtime.h>
#include <math.h>

#define BB 8
#define SS 2048
#define DDIM 256
#define HH 4
#define DH 64
#define NROWS (BB*SS)   // 16384

// ---------------- scratch (static device allocations; no cudaMalloc) -------
__device__ float g_qkv[(size_t)NROWS*768];      // [B*S, 768] interleaved (h,d,3)
__device__ float g_q  [(size_t)NROWS*DDIM];     // [B,H,S,Dh]
__device__ float g_k  [(size_t)NROWS*DDIM];     // [B,H,S,Dh]
__device__ float g_v  [(size_t)NROWS*DDIM];     // [B,H,S,Dh]
__device__ float g_ctx[(size_t)NROWS*DDIM];     // [B,S,D]
__device__ float g_msg[(size_t)NROWS*DDIM];     // [B,S,D]
__device__ float g_x1 [(size_t)NROWS*512];      // [B*S, 512]

// ---------------- helpers ---------------------------------------------------
__device__ __forceinline__ void mma8(float* d, const unsigned* a,
                                     unsigned b0, unsigned b1, const float* c) {
    asm volatile(
        "mma.sync.aligned.m16n8k8.row.col.f32.tf32.tf32.f32 "
        "{%0,%1,%2,%3}, {%4,%5,%6,%7}, {%8,%9}, {%10,%11,%12,%13};"
        : "=f"(d[0]), "=f"(d[1]), "=f"(d[2]), "=f"(d[3])
        : "r"(a[0]), "r"(a[1]), "r"(a[2]), "r"(a[3]), "r"(b0), "r"(b1),
          "f"(c[0]), "f"(c[1]), "f"(c[2]), "f"(c[3]));
}

__device__ __forceinline__ void cp16(void* smem_dst, const void* gmem_src) {
    unsigned s = (unsigned)__cvta_generic_to_shared(smem_dst);
    asm volatile("cp.async.cg.shared.global [%0], [%1], 16;\n"
                 :: "r"(s), "l"(gmem_src));
}

// exp(0.125*x) via exp2 polynomial (no MUFU). Valid for x <= 0.
// scale 0.125 folded into the log2(e) constant.
__device__ __forceinline__ float fast_exp_s(float x) {
    float t = fmaxf(x * 0.18033688011112043f, -126.0f);
    int   i = __float2int_rd(t);
    float f = t - (float)i;
    float p = 1.33336498402e-3f;
    p = fmaf(p, f, 9.81094791730e-3f);
    p = fmaf(p, f, 5.54906055893e-2f);
    p = fmaf(p, f, 2.40226506959e-1f);
    p = fmaf(p, f, 6.93147180560e-1f);
    p = fmaf(p, f, 1.0f);
    return p * __int_as_float((i + 127) << 23);
}

// ---------------- tf32 GEMM, cp.async double-buffered ----------------------
// C[M,N] = A[M,K] @ W[N,K]^T + bias (+res). A split in K at `split` (A0/A1).
// Block tile 128x128, warp tile 64x32 (8 warps as 2x4), K-chunk 32.
__global__ void __launch_bounds__(256) gemm_ca(
    const float* __restrict__ A0, const float* __restrict__ A1, int split,
    const float* __restrict__ W, const float* __restrict__ bias,
    const float* __restrict__ res, float* __restrict__ C, int K, int N)
{
    extern __shared__ float sm[];
    float* Asm = sm;           // [2][4096]
    float* Wsm = sm + 8192;    // [2][4096]
    int tid = threadIdx.x;
    int wid = tid >> 5, lane = tid & 31;
    int g = lane >> 2, t = lane & 3;
    int wm = wid & 1, wn = wid >> 1;          // 2 x 4 warp grid
    int rowBase = blockIdx.y * 128;
    int colBase = blockIdx.x * 128;
    int sA1 = K - split;
    int KT = K / 32;
    float acc[4][4][4] = {};

    auto copy_tiles = [&](int kt, int st) {
        int k0 = kt * 32;
        #pragma unroll
        for (int i = 0; i < 4; i++) {
            int e = tid + i*256;              // 0..1023
            int r = e >> 3, grp = e & 7;
            int kg = k0 + grp*4;
            const float* srcA = (kg < split)
                ? (A0 + (size_t)(rowBase+r)*split + kg)
                : (A1 + (size_t)(rowBase+r)*sA1 + (kg - split));
            cp16(&Asm[st*4096 + r*32 + ((grp ^ (r & 7)) << 2)], srcA);
            const float* srcW = W + (size_t)(colBase+r)*K + kg;
            cp16(&Wsm[st*4096 + r*32 + ((grp ^ (r & 7)) << 2)], srcW);
        }
    };

    copy_tiles(0, 0);
    asm volatile("cp.async.commit_group;\n");

    for (int kt = 0; kt < KT; kt++) {
        if (kt + 1 < KT) {
            copy_tiles(kt+1, (kt+1) & 1);
            asm volatile("cp.async.commit_group;\n");
            asm volatile("cp.async.wait_group 1;\n");
        } else {
            asm volatile("cp.async.wait_group 0;\n");
        }
        __syncthreads();
        const float* Ab = Asm + (kt & 1)*4096;
        const float* Wb = Wsm + (kt & 1)*4096;
        #pragma unroll
        for (int k8 = 0; k8 < 32; k8 += 8) {
            int sw1 = (((k8 >> 2)     ^ g) << 2) + t;
            int sw2 = ((((k8 >> 2)+1) ^ g) << 2) + t;
            unsigned a[4][4];
            #pragma unroll
            for (int mi = 0; mi < 4; mi++) {
                int r = wm*64 + mi*16 + g;
                a[mi][0] = __float_as_uint(Ab[r*32 + sw1]);
                a[mi][1] = __float_as_uint(Ab[(r+8)*32 + sw1]);
                a[mi][2] = __float_as_uint(Ab[r*32 + sw2]);
                a[mi][3] = __float_as_uint(Ab[(r+8)*32 + sw2]);
            }
            unsigned b[4][2];
            #pragma unroll
            for (int ni = 0; ni < 4; ni++) {
                int c = wn*32 + ni*8 + g;
                b[ni][0] = __float_as_uint(Wb[c*32 + sw1]);
                b[ni][1] = __float_as_uint(Wb[c*32 + sw2]);
            }
            #pragma unroll
            for (int mi = 0; mi < 4; mi++)
                #pragma unroll
                for (int ni = 0; ni < 4; ni++)
                    mma8(acc[mi][ni], a[mi], b[ni][0], b[ni][1], acc[mi][ni]);
        }
        __syncthreads();
    }

    #pragma unroll
    for (int mi = 0; mi < 4; mi++) {
        int r0 = rowBase + wm*64 + mi*16 + g;
        #pragma unroll
        for (int ni = 0; ni < 4; ni++) {
            int c = colBase + wn*32 + ni*8 + 2*t;
            float b0 = bias[c], b1 = bias[c+1];
            float v00 = acc[mi][ni][0] + b0, v01 = acc[mi][ni][1] + b1;
            float v10 = acc[mi][ni][2] + b0, v11 = acc[mi][ni][3] + b1;
            if (res) {
                v00 += res[(size_t)r0*N + c];     v01 += res[(size_t)r0*N + c + 1];
                v10 += res[(size_t)(r0+8)*N + c]; v11 += res[(size_t)(r0+8)*N + c + 1];
            }
            *(float2*)&C[(size_t)r0*N + c]     = make_float2(v00, v01);
            *(float2*)&C[(size_t)(r0+8)*N + c] = make_float2(v10, v11);
        }
    }
}

// ---------------- rotary + split qkv into [B,H,S,Dh] -----------------------
__global__ void rotary_split(const float* __restrict__ kp) {
    int idx = blockIdx.x*blockDim.x + threadIdx.x;
    int i   = idx & 31;
    int h   = (idx >> 5) & 3;
    int row = idx >> 7;
    const float* qkv = g_qkv + (size_t)row*768 + h*192 + i*6;
    float q0 = qkv[0], k0 = qkv[1], v0 = qkv[2];
    float q1 = qkv[3], k1 = qkv[4], v1 = qkv[5];
    int d = i*2;
    size_t co = (size_t)row*DH + d;
    float c0 = kp[co],                    c1 = kp[co+1];
    float s0 = kp[(size_t)BB*SS*DH + co], s1 = kp[(size_t)BB*SS*DH + co + 1];
    int b = row >> 11;
    int s = row & 2047;
    size_t o = (((size_t)(b*HH + h))*SS + s)*DH + d;
    g_q[o]   = q0*c0 - q1*s0;
    g_q[o+1] = q1*c1 + q0*s1;
    g_k[o]   = k0*c0 - k1*s0;
    g_k[o+1] = k1*c1 + k0*s1;
    g_v[o]   = v0;
    g_v[o+1] = v1;
}

// ---------------- flash attention, tf32 mma, cp.async + Q-in-regs ----------
// Br=128, Bc=64, 8 warps x 16 q-rows. Q fragments held in registers for the
// whole kt loop; P tile overlays the Q smem buffer (freed after fragment
// load). K/V double-buffered via cp.async. 2 CTAs/SM.
// smem floats: QP[128*72] | K[2][64*72] | V[2][64*72] = 27648 floats (108KB)
__global__ void __launch_bounds__(256, 2) flash_attn() {
    extern __shared__ float sh[];
    float* Qs = sh;                        // [128][72], reused as P after prologue
    float* Ps = sh;
    float* Ks = sh + 9216;                 // [2][64][72]
    float* Vs = sh + 18432;                // [2][64][72]
    int tid = threadIdx.x, wid = tid >> 5, lane = tid & 31;
    int g = lane >> 2, t = lane & 3;
    int bh = blockIdx.y;
    int q0 = blockIdx.x * 128;
    size_t base = (size_t)bh * SS * DH;
    int qrow = wid * 16;

    auto copy_kv = [&](int kt, int st) {
        #pragma unroll
        for (int i = 0; i < 4; i++) {
            int e = tid + i*256;           // 0..1023
            int r = e >> 4, c4 = (e & 15)*4;
            size_t gk = base + (size_t)(kt*64 + r)*DH + c4;
            cp16(&Ks[st*4608 + r*72 + c4], g_k + gk);
            cp16(&Vs[st*4608 + r*72 + c4], g_v + gk);
        }
    };

    // prologue: Q tile + first K/V tile
    #pragma unroll
    for (int i = 0; i < 8; i++) {
        int e = tid + i*256;               // 0..2047
        int r = e >> 4, c4 = (e & 15)*4;
        cp16(&Qs[r*72 + c4], g_q + base + (size_t)(q0 + r)*DH + c4);
    }
    copy_kv(0, 0);
    asm volatile("cp.async.commit_group;\n");
    asm volatile("cp.async.wait_group 0;\n");
    __syncthreads();

    // hoist Q fragments into registers (loop-invariant over kt)
    unsigned qf[8][4];
    #pragma unroll
    for (int ki = 0; ki < 8; ki++) {
        int k8 = ki * 8;
        qf[ki][0] = __float_as_uint(Qs[(qrow+g)*72 + k8 + t]);
        qf[ki][1] = __float_as_uint(Qs[(qrow+g+8)*72 + k8 + t]);
        qf[ki][2] = __float_as_uint(Qs[(qrow+g)*72 + k8 + t + 4]);
        qf[ki][3] = __float_as_uint(Qs[(qrow+g+8)*72 + k8 + t + 4]);
    }
    __syncthreads();   // all warps done reading Q; smem now free for P

    float m0 = -1e30f, m1 = -1e30f, l0 = 0.f, l1 = 0.f;
    float o[8][4];
    #pragma unroll
    for (int n = 0; n < 8; n++)
        #pragma unroll
        for (int j = 0; j < 4; j++) o[n][j] = 0.f;

    for (int kt = 0; kt < SS/64; kt++) {
        if (kt + 1 < SS/64) {
            copy_kv(kt+1, (kt+1) & 1);
            asm volatile("cp.async.commit_group;\n");
            asm volatile("cp.async.wait_group 1;\n");
        } else {
            asm volatile("cp.async.wait_group 0;\n");
        }
        __syncthreads();
        const float* Kb = Ks + (kt & 1)*4608;
        const float* Vb = Vs + (kt & 1)*4608;

        // S = Q K^T (raw logits; scale folded into exp)
        float sc[8][4] = {};
        #pragma unroll
        for (int ki = 0; ki < 8; ki++) {
            int k8 = ki * 8;
            #pragma unroll
            for (int n = 0; n < 8; n++) {
                unsigned b0 = __float_as_uint(Kb[(n*8+g)*72 + k8 + t]);
                unsigned b1 = __float_as_uint(Kb[(n*8+g)*72 + k8 + t + 4]);
                mma8(sc[n], qf[ki], b0, b1, sc[n]);
            }
        }

        // online softmax (rows qrow+g and qrow+g+8)
        float mx0 = -1e30f, mx1 = -1e30f;
        #pragma unroll
        for (int n = 0; n < 8; n++) {
            mx0 = fmaxf(mx0, fmaxf(sc[n][0], sc[n][1]));
            mx1 = fmaxf(mx1, fmaxf(sc[n][2], sc[n][3]));
        }
        #pragma unroll
        for (int off = 1; off <= 2; off <<= 1) {
            mx0 = fmaxf(mx0, __shfl_xor_sync(0xffffffffu, mx0, off));
            mx1 = fmaxf(mx1, __shfl_xor_sync(0xffffffffu, mx1, off));
        }
        float mn0 = fmaxf(m0, mx0), mn1 = fmaxf(m1, mx1);
        float al0 = fast_exp_s(m0 - mn0), al1 = fast_exp_s(m1 - mn1);
        m0 = mn0; m1 = mn1;
        float s0 = 0.f, s1 = 0.f;
        #pragma unroll
        for (int n = 0; n < 8; n++) {
            float p00 = fast_exp_s(sc[n][0] - m0);
            float p01 = fast_exp_s(sc[n][1] - m0);
            float p10 = fast_exp_s(sc[n][2] - m1);
            float p11 = fast_exp_s(sc[n][3] - m1);
            s0 += p00 + p01; s1 += p10 + p11;
            Ps[(qrow+g)*72 + n*8 + 2*t]       = p00;
            Ps[(qrow+g)*72 + n*8 + 2*t + 1]   = p01;
            Ps[(qrow+g+8)*72 + n*8 + 2*t]     = p10;
            Ps[(qrow+g+8)*72 + n*8 + 2*t + 1] = p11;
        }
        #pragma unroll
        for (int off = 1; off <= 2; off <<= 1) {
            s0 += __shfl_xor_sync(0xffffffffu, s0, off);
            s1 += __shfl_xor_sync(0xffffffffu, s1, off);
        }
        l0 = l0*al0 + s0;
        l1 = l1*al1 + s1;
        #pragma unroll
        for (int n = 0; n < 8; n++) {
            o[n][0] *= al0; o[n][1] *= al0;
            o[n][2] *= al1; o[n][3] *= al1;
        }
        __syncwarp();

        // O += P V
        #pragma unroll
        for (int k8 = 0; k8 < 64; k8 += 8) {
            unsigned a[4];
            a[0] = __float_as_uint(Ps[(qrow+g)*72 + k8 + t]);
            a[1] = __float_as_uint(Ps[(qrow+g+8)*72 + k8 + t]);
            a[2] = __float_as_uint(Ps[(qrow+g)*72 + k8 + t + 4]);
            a[3] = __float_as_uint(Ps[(qrow+g+8)*72 + k8 + t + 4]);
            #pragma unroll
            for (int n = 0; n < 8; n++) {
                unsigned b0 = __float_as_uint(Vb[(k8+t)*72 + n*8 + g]);
                unsigned b1 = __float_as_uint(Vb[(k8+t+4)*72 + n*8 + g]);
                mma8(o[n], a, b0, b1, o[n]);
            }
        }
        __syncthreads();
    }

    float inv0 = 1.f / l0, inv1 = 1.f / l1;
    int b = bh >> 2, h = bh & 3;
    int r0 = q0 + qrow + g;
    #pragma unroll
    for (int n = 0; n < 8; n++) {
        int c = h*64 + n*8 + 2*t;
        *(float2*)&g_ctx[((size_t)(b*SS + r0))*DDIM + c] =
            make_float2(o[n][0]*inv0, o[n][1]*inv0);
        *(float2*)&g_ctx[((size_t)(b*SS + r0 + 8))*DDIM + c] =
            make_float2(o[n][2]*inv1, o[n][3]*inv1);
    }
}

// ---------------- LayerNorm + exact GELU, in place on g_x1 ------------------
__global__ void ln_gelu(const float* __restrict__ lng, const float* __restrict__ lnb) {
    int row = blockIdx.x*8 + (threadIdx.x >> 5);
    int lane = threadIdx.x & 31;
    float* x = g_x1 + (size_t)row*512;
    float4 v[4];
    float s = 0.f, s2 = 0.f;
    #pragma unroll
    for (int j = 0; j < 4; j++) {
        v[j] = *(float4*)&x[4*(lane + 32*j)];
        s  += v[j].x + v[j].y + v[j].z + v[j].w;
        s2 += v[j].x*v[j].x + v[j].y*v[j].y + v[j].z*v[j].z + v[j].w*v[j].w;
    }
    #pragma unroll
    for (int off = 16; off >= 1; off >>= 1) {
        s  += __shfl_xor_sync(0xffffffffu, s,  off);
        s2 += __shfl_xor_sync(0xffffffffu, s2, off);
    }
    float mean = s * (1.f/512.f);
    float var  = s2 * (1.f/512.f) - mean*mean;
    float inv  = rsqrtf(var + 1e-5f);
    #pragma unroll
    for (int j = 0; j < 4; j++) {
        int c = 4*(lane + 32*j);
        float* pv = (float*)&v[j];
        #pragma unroll
        for (int q = 0; q < 4; q++) {
            float y = (pv[q] - mean)*inv*lng[c+q] + lnb[c+q];
            pv[q] = 0.5f*y*(1.f + erff(y*0.7071067811865476f));
        }
        *(float4*)&x[c] = v[j];
    }
}

// ---------------------------------------------------------------------------
extern "C" void kernel_launch(void* const* d_in, const int* in_sizes, int n_in,
                              void* d_out, int out_size) {
    const float* desc   = (const float*)d_in[0];
    const float* kp     = (const float*)d_in[1];
    const float* Wqkv_w = (const float*)d_in[2];
    const float* Wqkv_b = (const float*)d_in[3];
    const float* Wo_w   = (const float*)d_in[4];
    const float* Wo_b   = (const float*)d_in[5];
    const float* W1_w   = (const float*)d_in[6];
    const float* W1_b   = (const float*)d_in[7];
    const float* lng    = (const float*)d_in[8];
    const float* lnb    = (const float*)d_in[9];
    const float* W2_w   = (const float*)d_in[10];
    const float* W2_b   = (const float*)d_in[11];
    float* out = (float*)d_out;

    void *p_qkv, *p_ctx, *p_msg, *p_x1;
    cudaGetSymbolAddress(&p_qkv, g_qkv);
    cudaGetSymbolAddress(&p_ctx, g_ctx);
    cudaGetSymbolAddress(&p_msg, g_msg);
    cudaGetSymbolAddress(&p_x1,  g_x1);

    cudaFuncSetAttribute(flash_attn, cudaFuncAttributeMaxDynamicSharedMemorySize,
                         27648*4);
    cudaFuncSetAttribute(gemm_ca, cudaFuncAttributeMaxDynamicSharedMemorySize,
                         65536);

    // 1) qkv = desc @ Wqkv^T + b           [16384, 768]
    gemm_ca<<<dim3(6, 128), 256, 65536>>>(desc, desc, 256, Wqkv_w, Wqkv_b,
                                          nullptr, (float*)p_qkv, 256, 768);
    // 2) rotary + split -> q/k/v [B,H,S,Dh]
    rotary_split<<<(NROWS*HH*32)/256, 256>>>(kp);
    // 3) flash attention -> ctx [B,S,D]
    flash_attn<<<dim3(SS/128, BB*HH), 256, 27648*4>>>();
    // 4) msg = ctx @ Wo^T + b              [16384, 256]
    gemm_ca<<<dim3(2, 128), 256, 65536>>>((const float*)p_ctx, (const float*)p_ctx, 256,
                                          Wo_w, Wo_b, nullptr, (float*)p_msg, 256, 256);
    // 5) x1 = [desc|msg] @ W1^T + b        [16384, 512]  (concat fused into K)
    gemm_ca<<<dim3(4, 128), 256, 65536>>>(desc, (const float*)p_msg, 256,
                                          W1_w, W1_b, nullptr, (float*)p_x1, 512, 512);
    // 6) LayerNorm + exact GELU in place
    ln_gelu<<<NROWS/8, 256>>>(lng, lnb);
    // 7) out = desc + x1 @ W2^T + b        [16384, 256]
    gemm_ca<<<dim3(2, 128), 256, 65536>>>((const float*)p_x1, (const float*)p_x1, 512,
                                          W2_w, W2_b, desc, out, 512, 256);
}